// round 3
// baseline (speedup 1.0000x reference)
#include <cuda_runtime.h>

#define NB 32
#define NA 5
#define NC 80
#define NH 76
#define NW 76
#define HW (NH*NW)            // 5776
#define MAXT 50
#define NCELL (NB*NA*HW)      // 924160
#define CHS (NA*(5+NC))       // 425
#define CPB (NA*HW)           // cells per batch = 28880
#define BWPB 904              // bit-words per batch (28880/32 = 902.5 -> pad 904)

__constant__ float c_aw[5] = {1.3221f, 3.19275f, 5.05587f, 9.47112f, 11.2364f};
__constant__ float c_ah[5] = {1.73145f, 4.00944f, 8.09892f, 4.84053f, 10.0071f};

// scratch (static device globals — no allocation)
__device__ unsigned g_bits[NB*BWPB];   // per-cell "excluded from noobj" bit, padded per batch
#define TR 16
// per (b,t): [0]gx [1]gy [2]gw [3]gh [4]tx [5]ty [6]tw [7]th [8]tconf
//            (int)[9]tcls (int)[10]valid (int)[11]winner (int)[12]obase
__device__ float  g_trec[NB*MAXT*TR];
__device__ double g_acc;

__device__ __forceinline__ float sigm(float v) {
    return __fdividef(1.f, 1.f + __expf(-v));
}

// ---------------------------------------------------------------- prep: clear bits + per-target records + winner bits
// One block per batch b (64 threads). Bit region per batch is private -> intra-block ordering only.
__global__ void k_prep(const float* __restrict__ out, const float* __restrict__ tgt) {
    int b = blockIdx.x;
    int t = threadIdx.x;

    // clear this batch's bit region
    for (int w = t; w < BWPB; w += blockDim.x) g_bits[b*BWPB + w] = 0u;
    if (b == 0 && t == 0) g_acc = 0.0;

    __shared__ unsigned char ok[MAXT];
    __shared__ int s_cell[MAXT];
    __shared__ int s_val[MAXT];
    if (t < MAXT) {
        float cx = tgt[b*MAXT*5 + t*5 + 1];
        ok[t] = (cx != 0.f) ? 1 : 0;
    }
    __syncthreads();   // clear done + ok[] ready
    if (t >= MAXT) return;

    int valid = 1;
    for (int u = 0; u <= t; u++) valid &= (int)ok[u];   // cumprod semantics

    const float* tp = tgt + b*MAXT*5 + t*5;
    float cls = tp[0];
    float gx = tp[1]*NW, gy = tp[2]*NH, gw = tp[3]*NW, gh = tp[4]*NH;

    // best anchor by shape IoU (first index wins ties, strict >)
    float best = -1.f; int bn = 0;
    #pragma unroll
    for (int a = 0; a < NA; a++) {
        float aw = c_aw[a], ah = c_ah[a];
        float inter = fminf(gw, aw) * fminf(gh, ah);
        float uni   = gw*gh + aw*ah - inter;
        float iou   = __fdividef(inter, uni);
        if (iou > best) { best = iou; bn = a; }
    }

    int gi = (int)gx; gi = max(0, min(NW-1, gi));
    int gj = (int)gy; gj = max(0, min(NH-1, gj));

    int cib   = ((bn*NH) + gj)*NW + gi;                 // cell-in-batch
    int obase = (b*CHS + bn*(5+NC))*HW + gj*NW + gi;    // output-tensor offset

    s_cell[t] = cib;
    s_val[t]  = valid;
    __syncthreads();

    // winner = valid and no later valid target hits the same cell (last-write-wins)
    int winner = valid;
    for (int u = t+1; u < MAXT; u++)
        if (s_val[u] && s_cell[u] == s_cell[t]) { winner = 0; break; }

    // matched pred box (gather 4 values)
    float o0 = out[obase], o1 = out[obase+HW], o2 = out[obase+2*HW], o3 = out[obase+3*HW];
    float mpx = sigm(o0) + (float)gi;
    float mpy = sigm(o1) + (float)gj;
    float mpw = __expf(o2) * c_aw[bn];
    float mph = __expf(o3) * c_ah[bn];

    // t_iou = IoU(gt_box, matched_pred)
    float mx = fminf(gx - 0.5f*gw, mpx - 0.5f*mpw);
    float Mx = fmaxf(gx + 0.5f*gw, mpx + 0.5f*mpw);
    float my = fminf(gy - 0.5f*gh, mpy - 0.5f*mph);
    float My = fmaxf(gy + 0.5f*gh, mpy + 0.5f*mph);
    float cw = gw + mpw - (Mx - mx);
    float ch = gh + mph - (My - my);
    float inter = (cw <= 0.f || ch <= 0.f) ? 0.f : cw*ch;
    float uni   = gw*gh + mpw*mph - inter;
    float t_iou = __fdividef(inter, uni);

    float* r = g_trec + (b*MAXT + t)*TR;
    r[0] = gx; r[1] = gy; r[2] = gw; r[3] = gh;
    r[4] = gx - (float)gi;
    r[5] = gy - (float)gj;
    r[6] = __logf(__fdividef(gw, c_aw[bn]));
    r[7] = __logf(__fdividef(gh, c_ah[bn]));
    r[8] = t_iou;
    ((int*)r)[9]  = (int)cls;
    ((int*)r)[10] = valid;
    ((int*)r)[11] = winner;
    ((int*)r)[12] = obase;

    if (winner)
        atomicOr(&g_bits[b*BWPB + (cib >> 5)], 1u << (cib & 31));
}

// ---------------------------------------------------------------- main: total conf^2 stream + matched loss + raster
// One block per (b,t). 256 threads.
__global__ void k_main(const float* __restrict__ out) {
    int blk = blockIdx.x;
    int b = blk / MAXT, t = blk - b*MAXT;
    int tid = threadIdx.x;

    float accA = 0.f;        // net sum of conf^2 (x0.5 at end)
    float contribM = 0.f;    // matched terms (already scaled)

    // ---- phase A: this block's slice of the full conf^2 sum ----
    {
        const int TOT4 = NCELL/4;                       // 231040
        const int per  = (TOT4 + (NB*MAXT) - 1)/(NB*MAXT);  // 145
        int start = blk*per;
        int end   = min(TOT4, start + per);
        for (int q = start + tid; q < end; q += blockDim.x) {
            int idx4 = q*4;
            int p  = idx4 / HW;
            int hw = idx4 - p*HW;
            int bb = p / NA, aa = p - bb*NA;
            float4 c4 = *(const float4*)(out + ((size_t)(bb*CHS + aa*(5+NC) + 4))*HW + hw);
            float s0 = sigm(c4.x), s1 = sigm(c4.y), s2 = sigm(c4.z), s3 = sigm(c4.w);
            accA += s0*s0 + s1*s1 + s2*s2 + s3*s3;
        }
    }

    const float* r = g_trec + (b*MAXT + t)*TR;
    int valid  = ((const int*)r)[10];
    int winner = ((const int*)r)[11];
    int obase  = ((const int*)r)[12];

    // ---- phase B: matched-cell loss (winner blocks; 3 warps do 80-wide log-softmax) ----
    if (winner) {
        __shared__ float sm[3], ss[3];
        int lane = tid & 31, wid = tid >> 5;
        const float* lg = out + obase + 5*HW;
        if (tid < 96) {
            unsigned mask = 0xFFFFFFFFu;
            float v = (tid < NC) ? __ldg(lg + tid*HW) : -1e30f;
            float m = v;
            #pragma unroll
            for (int off = 16; off > 0; off >>= 1) m = fmaxf(m, __shfl_xor_sync(mask, m, off));
            if (lane == 0) sm[wid] = m;
        }
        __syncthreads();
        if (tid < 96) {
            unsigned mask = 0xFFFFFFFFu;
            float mx = fmaxf(sm[0], fmaxf(sm[1], sm[2]));
            float v = (tid < NC) ? __ldg(lg + tid*HW) : -1e30f;
            float e = (tid < NC) ? __expf(v - mx) : 0.f;
            #pragma unroll
            for (int off = 16; off > 0; off >>= 1) e += __shfl_xor_sync(mask, e, off);
            if (lane == 0) ss[wid] = e;
        }
        __syncthreads();
        if (tid == 0) {
            float mx = fmaxf(sm[0], fmaxf(sm[1], sm[2]));
            float s  = ss[0] + ss[1] + ss[2];
            int tc = ((const int*)r)[9];
            float ce = mx + __logf(s) - __ldg(lg + tc*HW);

            float o0 = out[obase], o1 = out[obase+HW];
            float o2 = out[obase+2*HW], o3 = out[obase+3*HW];
            float conf = sigm(out[obase+4*HW]);
            float dx = sigm(o0) - r[4];
            float dy = sigm(o1) - r[5];
            float dw = o2 - r[6];
            float dh = o3 - r[7];
            float dc = conf - r[8];
            contribM = 0.5f*(dx*dx + dy*dy + dw*dw + dh*dh) + 2.5f*dc*dc + ce;
            accA -= conf*conf;   // remove this cell's noobj contribution (bit was set in prep)
        }
    }

    // ---- phase C: raster IoU>0.6 window with dedup subtraction ----
    // Safe bound: IoU>0.6 => |px-gx| < 0.2(pw+gw) < 0.5334*gw  (pw < gw/0.6); use 0.54 margin.
    if (valid) {
        float gx = r[0], gy = r[1], gw = r[2], gh = r[3];
        float gx0 = gx - 0.5f*gw, gx1 = gx + 0.5f*gw;
        float gy0 = gy - 0.5f*gh, gy1 = gy + 0.5f*gh;
        float g375 = 0.375f * gw * gh;

        int i0 = max(0,    (int)floorf(gx - 0.54f*gw) - 1);
        int i1 = min(NW-1, (int)floorf(gx + 0.54f*gw) + 1);
        int j0 = max(0,    (int)floorf(gy - 0.54f*gh) - 1);
        int j1 = min(NH-1, (int)floorf(gy + 0.54f*gh) + 1);
        int wi = i1 - i0 + 1, wj = j1 - j0 + 1;
        int win = wi * wj;
        int tot = win * NA;

        for (int k = tid; k < tot; k += blockDim.x) {
            int a  = k / win;
            int rr = k - a*win;
            int jq = rr / wi;
            int j  = j0 + jq;
            int i  = i0 + rr - jq*wi;
            int base = (b*CHS + a*(5+NC))*HW + j*NW + i;
            float o0 = __ldg(out+base),      o1 = __ldg(out+base+HW);
            float o2 = __ldg(out+base+2*HW), o3 = __ldg(out+base+3*HW);
            float px = sigm(o0) + (float)i;
            float py = sigm(o1) + (float)j;
            float pw = __expf(o2) * c_aw[a];
            float ph = __expf(o3) * c_ah[a];
            float cw = pw + gw - (fmaxf(px + 0.5f*pw, gx1) - fminf(px - 0.5f*pw, gx0));
            float ch = ph + gh - (fmaxf(py + 0.5f*ph, gy1) - fminf(py - 0.5f*ph, gy0));
            if (cw > 0.f && ch > 0.f) {
                float inter = cw * ch;
                // iou > 0.6  <=>  inter > 0.375*(parea+garea)
                if (inter > 0.375f*pw*ph + g375) {
                    int cib = (a*NH + j)*NW + i;
                    unsigned bit = 1u << (cib & 31);
                    unsigned old = atomicOr(&g_bits[b*BWPB + (cib >> 5)], bit);
                    if (!(old & bit)) {
                        float cv = sigm(__ldg(out + base + 4*HW));
                        accA -= cv*cv;
                    }
                }
            }
        }
    }

    // ---- block reduction -> double atomic ----
    float v = 0.5f*accA + contribM;
    unsigned mask = 0xFFFFFFFFu;
    #pragma unroll
    for (int off = 16; off > 0; off >>= 1) v += __shfl_down_sync(mask, v, off);
    __shared__ float sw[8];
    int lane = tid & 31, wid = tid >> 5;
    if (lane == 0) sw[wid] = v;
    __syncthreads();
    if (wid == 0) {
        v = (lane < (int)(blockDim.x >> 5)) ? sw[lane] : 0.f;
        #pragma unroll
        for (int off = 4; off > 0; off >>= 1) v += __shfl_down_sync(mask, v, off);
        if (lane == 0) atomicAdd(&g_acc, (double)v);
    }
}

__global__ void k_finish(float* res) {
    res[0] = (float)g_acc;
}

// ---------------------------------------------------------------- launch
extern "C" void kernel_launch(void* const* d_in, const int* in_sizes, int n_in,
                              void* d_out, int out_size) {
    const float* out = (const float*)d_in[0];   // (32, 425, 76, 76)
    const float* tgt = (const float*)d_in[1];   // (32, 250)
    float* res = (float*)d_out;

    k_prep  <<<NB, 64>>>(out, tgt);
    k_main  <<<NB*MAXT, 256>>>(out);
    k_finish<<<1, 1>>>(res);
}

// round 4
// speedup vs baseline: 1.2265x; 1.2265x over previous
#include <cuda_runtime.h>

#define NB 32
#define NA 5
#define NC 80
#define NH 76
#define NW 76
#define HW (NH*NW)            // 5776
#define HW4 (HW/4)            // 1444
#define MAXT 50
#define NCELL (NB*NA*HW)      // 924160
#define CHS (NA*(5+NC))       // 425
#define CPB (NA*HW)           // 28880 cells per batch
#define NBLK (NB*MAXT)        // 1600

__constant__ float c_aw[5] = {1.3221f, 3.19275f, 5.05587f, 9.47112f, 11.2364f};
__constant__ float c_ah[5] = {1.73145f, 4.00944f, 8.09892f, 4.84053f, 10.0071f};

// static scratch — no allocation. Epoch protocol: no clearing pass needed.
__device__ unsigned g_mark[NCELL];      // last-claim epoch per cell (BSS zero)
__device__ unsigned g_epoch = 1;        // != 0 initially
__device__ double   g_acc;              // BSS zero; reset by k_finish each run

__device__ __forceinline__ float sigm(float v) {
    return __fdividef(1.f, 1.f + __expf(-v));
}

// ================================================================ main
// One block per (b,t), 256 threads. Does EVERYTHING:
//   A) slice of global sum of conf^2 over all cells
//   B) matched-cell loss (winner targets) + exclusion claim
//   C) raster of IoU>0.6 window + exclusion claims
// Excluded cells subtract conf^2 exactly once via atomicExch(epoch) claim.
__global__ __launch_bounds__(256) void k_main(const float* __restrict__ out,
                                              const float* __restrict__ tgt) {
    int blk = blockIdx.x;
    int b = blk / MAXT, t = blk - b*MAXT;
    int tid = threadIdx.x;
    unsigned ep = g_epoch;

    float accA = 0.f;       // net conf^2 sum (x0.5 at the end)
    float contribM = 0.f;   // matched terms (already scaled)

    // ---- phase A: this block's contiguous slice of the full conf^2 sum ----
    {
        const int per = (NCELL/4 + NBLK - 1) / NBLK;   // 145
        int q0 = blk * per;
        int q1 = min(NCELL/4, q0 + per);
        for (int q = q0 + tid; q < q1; q += 256) {
            int p   = q / HW4;              // b*5+a
            int hw4 = q - p*HW4;
            int bb  = p / NA, aa = p - bb*NA;
            float4 c4 = *(const float4*)(out + (size_t)(bb*CHS + aa*(5+NC) + 4)*HW + hw4*4);
            float s0 = sigm(c4.x), s1 = sigm(c4.y), s2 = sigm(c4.z), s3 = sigm(c4.w);
            accA += s0*s0 + s1*s1 + s2*s2 + s3*s3;
        }
    }

    // ---- recompute all 50 targets of batch b in shared memory ----
    __shared__ unsigned char s_ok[MAXT];
    __shared__ int   s_cell[MAXT];       // cell-in-batch of target u
    __shared__ float s_par[8];           // this block's target: gx gy gw gh (f) bn gi gj cls
    __shared__ int   s_vw[2];            // valid, winner

    if (tid < MAXT) {
        const float* tp = tgt + (b*MAXT + tid)*5;
        float cx = tp[1];
        s_ok[tid] = (cx != 0.f) ? 1 : 0;
        float gx = tp[1]*NW, gy = tp[2]*NH, gw = tp[3]*NW, gh = tp[4]*NH;
        float best = -1.f; int bn = 0;
        #pragma unroll
        for (int a = 0; a < NA; a++) {
            float aw = c_aw[a], ah = c_ah[a];
            float inter = fminf(gw, aw) * fminf(gh, ah);
            float iou   = __fdividef(inter, gw*gh + aw*ah - inter);
            if (iou > best) { best = iou; bn = a; }
        }
        int gi = max(0, min(NW-1, (int)gx));
        int gj = max(0, min(NH-1, (int)gy));
        s_cell[tid] = (bn*NH + gj)*NW + gi;
        if (tid == t) {
            s_par[0] = gx; s_par[1] = gy; s_par[2] = gw; s_par[3] = gh;
            ((int*)s_par)[4] = bn; ((int*)s_par)[5] = gi; ((int*)s_par)[6] = gj;
            ((int*)s_par)[7] = (int)tp[0];
        }
    }
    __syncthreads();
    if (tid == 0) {
        int valid = 1;
        for (int u = 0; u <= t; u++) valid &= (int)s_ok[u];     // cumprod
        int winner = valid, run = valid;
        for (int u = t+1; u < MAXT; u++) {                       // last-write-wins
            run &= (int)s_ok[u];
            if (run && s_cell[u] == s_cell[t]) { winner = 0; break; }
        }
        s_vw[0] = valid; s_vw[1] = winner;
    }
    __syncthreads();

    int valid  = s_vw[0];
    int winner = s_vw[1];
    int bn = ((const int*)s_par)[4];
    int gi = ((const int*)s_par)[5];
    int gj = ((const int*)s_par)[6];
    int obase = (b*CHS + bn*(5+NC))*HW + gj*NW + gi;

    // ---- phase B: matched-cell loss (winner blocks; 3 warps, 80-wide log-softmax) ----
    if (winner) {
        __shared__ float sm[3], ss[3];
        int lane = tid & 31, wid = tid >> 5;
        const float* lg = out + obase + 5*HW;
        if (tid < 96) {
            unsigned mask = 0xFFFFFFFFu;
            float v = (tid < NC) ? __ldg(lg + tid*HW) : -1e30f;
            float m = v;
            #pragma unroll
            for (int off = 16; off > 0; off >>= 1) m = fmaxf(m, __shfl_xor_sync(mask, m, off));
            if (lane == 0) sm[wid] = m;
        }
        __syncthreads();
        if (tid < 96) {
            unsigned mask = 0xFFFFFFFFu;
            float mx = fmaxf(sm[0], fmaxf(sm[1], sm[2]));
            float v = (tid < NC) ? __ldg(lg + tid*HW) : -1e30f;
            float e = (tid < NC) ? __expf(v - mx) : 0.f;
            #pragma unroll
            for (int off = 16; off > 0; off >>= 1) e += __shfl_xor_sync(mask, e, off);
            if (lane == 0) ss[wid] = e;
        }
        __syncthreads();
        if (tid == 0) {
            float gx = s_par[0], gy = s_par[1], gw = s_par[2], gh = s_par[3];
            float mxv = fmaxf(sm[0], fmaxf(sm[1], sm[2]));
            float s   = ss[0] + ss[1] + ss[2];
            int   tc  = ((const int*)s_par)[7];
            float ce  = mxv + __logf(s) - __ldg(lg + tc*HW);

            float o0 = out[obase],      o1 = out[obase+HW];
            float o2 = out[obase+2*HW], o3 = out[obase+3*HW];
            float conf = sigm(out[obase+4*HW]);
            // matched pred box -> t_iou
            float mpx = sigm(o0) + (float)gi;
            float mpy = sigm(o1) + (float)gj;
            float mpw = __expf(o2) * c_aw[bn];
            float mph = __expf(o3) * c_ah[bn];
            float lx = fminf(gx - 0.5f*gw, mpx - 0.5f*mpw);
            float Rx = fmaxf(gx + 0.5f*gw, mpx + 0.5f*mpw);
            float ly = fminf(gy - 0.5f*gh, mpy - 0.5f*mph);
            float Ry = fmaxf(gy + 0.5f*gh, mpy + 0.5f*mph);
            float cw = gw + mpw - (Rx - lx);
            float ch = gh + mph - (Ry - ly);
            float inter = (cw <= 0.f || ch <= 0.f) ? 0.f : cw*ch;
            float t_iou = __fdividef(inter, gw*gh + mpw*mph - inter);

            float dx = sigm(o0) - (gx - (float)gi);
            float dy = sigm(o1) - (gy - (float)gj);
            float dw = o2 - __logf(__fdividef(gw, c_aw[bn]));
            float dh = o3 - __logf(__fdividef(gh, c_ah[bn]));
            float dc = conf - t_iou;
            contribM = 0.5f*(dx*dx + dy*dy + dw*dw + dh*dh) + 2.5f*dc*dc + ce;

            // claim this cell: remove its conf^2 from the noobj stream (once)
            unsigned old = atomicExch(&g_mark[b*CPB + s_cell[t]], ep);
            if (old != ep) accA -= conf*conf;
        }
    }

    // ---- phase C: raster IoU>0.6 window, float4-vectorized along i ----
    // IoU>0.6 => |px-gx| < 0.2(pw+gw) < 0.5334*gw (since pw < gw/0.6); margin 0.54 + 1 cell.
    if (valid) {
        float gx = s_par[0], gy = s_par[1], gw = s_par[2], gh = s_par[3];
        float gx0 = gx - 0.5f*gw, gx1 = gx + 0.5f*gw;
        float gy0 = gy - 0.5f*gh, gy1 = gy + 0.5f*gh;
        float g375 = 0.375f * gw * gh;

        int i0 = max(0,    (int)floorf(gx - 0.54f*gw) - 1);
        int i1 = min(NW-1, (int)floorf(gx + 0.54f*gw) + 1);
        int j0 = max(0,    (int)floorf(gy - 0.54f*gh) - 1);
        int j1 = min(NH-1, (int)floorf(gy + 0.54f*gh) + 1);
        int i0a = i0 & ~3;                        // 4-aligned group start
        int nGi = (i1 - i0a + 4) >> 2;            // groups of 4 i (stay in-row: start <= 72)
        int wj  = j1 - j0 + 1;
        int perA = nGi * wj;
        int tot  = perA * NA;

        for (int k = tid; k < tot; k += 256) {
            int a  = k / perA;
            int rr = k - a*perA;
            int jq = rr / nGi;
            int j  = j0 + jq;
            int ib = i0a + ((rr - jq*nGi) << 2);
            int base = (b*CHS + a*(5+NC))*HW + j*NW + ib;
            float4 v0 = *(const float4*)(out + base);
            float4 v1 = *(const float4*)(out + base + HW);
            float4 v2 = *(const float4*)(out + base + 2*HW);
            float4 v3 = *(const float4*)(out + base + 3*HW);
            const float* p0 = &v0.x; const float* p1 = &v1.x;
            const float* p2 = &v2.x; const float* p3 = &v3.x;
            #pragma unroll
            for (int u = 0; u < 4; u++) {
                int i = ib + u;
                float px = sigm(p0[u]) + (float)i;
                float py = sigm(p1[u]) + (float)j;
                float pw = __expf(p2[u]) * c_aw[a];
                float ph = __expf(p3[u]) * c_ah[a];
                float cw = pw + gw - (fmaxf(px + 0.5f*pw, gx1) - fminf(px - 0.5f*pw, gx0));
                float ch = ph + gh - (fmaxf(py + 0.5f*ph, gy1) - fminf(py - 0.5f*ph, gy0));
                if (cw > 0.f && ch > 0.f) {
                    float inter = cw * ch;
                    if (inter > 0.375f*pw*ph + g375) {      // exact: iou > 0.6
                        int cib = (a*NH + j)*NW + i;
                        unsigned old = atomicExch(&g_mark[b*CPB + cib], ep);
                        if (old != ep) {
                            float cv = sigm(__ldg(out + base + 4*HW + u));
                            accA -= cv*cv;
                        }
                    }
                }
            }
        }
    }

    // ---- block reduction -> double atomic ----
    float v = 0.5f*accA + contribM;
    unsigned mask = 0xFFFFFFFFu;
    #pragma unroll
    for (int off = 16; off > 0; off >>= 1) v += __shfl_down_sync(mask, v, off);
    __shared__ float sw[8];
    int lane = tid & 31, wid = tid >> 5;
    if (lane == 0) sw[wid] = v;
    __syncthreads();
    if (wid == 0) {
        v = (lane < 8) ? sw[lane] : 0.f;
        #pragma unroll
        for (int off = 4; off > 0; off >>= 1) v += __shfl_down_sync(mask, v, off);
        if (lane == 0) atomicAdd(&g_acc, (double)v);
    }
}

// ================================================================ finish
__global__ void k_finish(float* res) {
    res[0] = (float)g_acc;
    g_acc = 0.0;          // ready for next replay
    g_epoch = g_epoch + 1;  // invalidate all marks for next replay
}

// ================================================================ launch
extern "C" void kernel_launch(void* const* d_in, const int* in_sizes, int n_in,
                              void* d_out, int out_size) {
    const float* out = (const float*)d_in[0];   // (32, 425, 76, 76)
    const float* tgt = (const float*)d_in[1];   // (32, 250)
    float* res = (float*)d_out;

    k_main  <<<NBLK, 256>>>(out, tgt);
    k_finish<<<1, 1>>>(res);
}